// round 6
// baseline (speedup 1.0000x reference)
#include <cuda_runtime.h>
#include <math.h>

// Problem dims
#define Bq      32
#define Dq      512
#define Hq      1024
#define FOURH   4096
#define KTOT    1536            // H + D combined reduction dim
#define KSPLIT  8
#define KCHUNK  (KTOT / KSPLIT) // 192
#define PSPLIT  32              // plastic i-splits per batch
#define PCHUNK  (Hq / PSPLIT)   // 32

#define GB      8               // batches per group
#define NGROUP  (Bq / GB)       // 4 groups
#define NGEMM   (32 * KSPLIT)   // 256 gemm blocks
#define NPLAST_G (GB * PSPLIT)  // 256 plastic blocks per group

// Scratch (static __device__ — no allocation)
__device__ float g_part[KSPLIT][Bq * FOURH];         // GEMM partials (4 MB)
__device__ float g_plastic_part[Bq * PSPLIT * Hq];   // plastic partials (4 MB)
__device__ float g_tanhg[Bq * Hq];                   // tanh(cell gate) (128 KB)

// ---------------------------------------------------------------------------
// Plastic partials for one group of GB batches (device function).
// partial[b,sp,h] = sum_{i in 32-chunk sp} h0[b,i]*alpha[i,h]*Hebb0[b,i,h]
// ---------------------------------------------------------------------------
__device__ __forceinline__
void plastic_body(int p, int b0, const float* __restrict__ h0,
                  const float* __restrict__ alpha, const float* __restrict__ Hebb0)
{
    __shared__ float h0s[PCHUNK];
    const int b  = b0 + (p >> 5);
    const int sp = p & 31;
    const int i0 = sp * PCHUNK;
    const int tid = threadIdx.x;

    if (tid < PCHUNK) h0s[tid] = h0[b * Hq + i0 + tid];
    __syncthreads();

    const float4* Ap = (const float4*)(alpha + (size_t)i0 * Hq) + tid;
    const float4* Hp = (const float4*)(Hebb0 + (size_t)b * Hq * Hq
                                             + (size_t)i0 * Hq) + tid;
    const int rs = Hq / 4;  // row stride in float4

    float4 acc = make_float4(0.f, 0.f, 0.f, 0.f);
    for (int i = 0; i < PCHUNK; i += 4) {
        float4 a0 = Ap[(size_t)(i + 0) * rs];
        float4 a1 = Ap[(size_t)(i + 1) * rs];
        float4 a2 = Ap[(size_t)(i + 2) * rs];
        float4 a3 = Ap[(size_t)(i + 3) * rs];
        float4 v0 = Hp[(size_t)(i + 0) * rs];
        float4 v1 = Hp[(size_t)(i + 1) * rs];
        float4 v2 = Hp[(size_t)(i + 2) * rs];
        float4 v3 = Hp[(size_t)(i + 3) * rs];
        float s0 = h0s[i], s1 = h0s[i+1], s2 = h0s[i+2], s3 = h0s[i+3];
        acc.x += s0*a0.x*v0.x; acc.y += s0*a0.y*v0.y; acc.z += s0*a0.z*v0.z; acc.w += s0*a0.w*v0.w;
        acc.x += s1*a1.x*v1.x; acc.y += s1*a1.y*v1.y; acc.z += s1*a1.z*v1.z; acc.w += s1*a1.w*v1.w;
        acc.x += s2*a2.x*v2.x; acc.y += s2*a2.y*v2.y; acc.z += s2*a2.z*v2.z; acc.w += s2*a2.w*v2.w;
        acc.x += s3*a3.x*v3.x; acc.y += s3*a3.y*v3.y; acc.z += s3*a3.z*v3.z; acc.w += s3*a3.w*v3.w;
    }
    float4* outp = (float4*)(g_plastic_part + (size_t)(b * PSPLIT + sp) * Hq);
    outp[tid] = acc;
}

// ---------------------------------------------------------------------------
// Group 0 fused: blocks [0,NGEMM) -> gemm partials, rest -> plastic for b 0..7
// ---------------------------------------------------------------------------
__global__ __launch_bounds__(256)
void k_group0(const float* __restrict__ x,  const float* __restrict__ h0,
              const float* __restrict__ Wh, const float* __restrict__ Wx,
              const float* __restrict__ alpha, const float* __restrict__ Hebb0)
{
    if (blockIdx.x >= NGEMM) {
        plastic_body(blockIdx.x - NGEMM, 0, h0, alpha, Hebb0);
    } else {
        // ---------------- gemm partials ----------------
        __shared__ float Ws[16][128];
        __shared__ float As[16][32];

        const int gid = blockIdx.x;
        const int jt  = gid & 31;       // j tile (128 wide)
        const int ks  = gid >> 5;       // k split (0..7)
        const int tid = threadIdx.x;
        const int tj  = tid & 31;
        const int tb  = tid >> 5;

        float acc[4][4];
#pragma unroll
        for (int i = 0; i < 4; i++)
#pragma unroll
            for (int j = 0; j < 4; j++) acc[i][j] = 0.f;

        const int k0base = ks * KCHUNK;
        const int jbase  = jt * 128;

        for (int t = 0; t < KCHUNK / 16; t++) {
            const int k0 = k0base + t * 16;
            __syncthreads();
#pragma unroll
            for (int r = 0; r < 8; r++) {
                int lin = r * 256 + tid;
                int kk = lin >> 7, j = lin & 127;
                int k = k0 + kk;
                Ws[kk][j] = (k < Hq) ? Wh[(size_t)k * FOURH + jbase + j]
                                     : Wx[(size_t)(k - Hq) * FOURH + jbase + j];
            }
#pragma unroll
            for (int r = 0; r < 2; r++) {
                int lin = r * 256 + tid;
                int kk = lin >> 5, b = lin & 31;
                int k = k0 + kk;
                As[kk][b] = (k < Hq) ? h0[b * Hq + k] : x[b * Dq + (k - Hq)];
            }
            __syncthreads();
#pragma unroll
            for (int kk = 0; kk < 16; kk++) {
                float4 a = *(const float4*)&As[kk][tb * 4];
                float4 w = *(const float4*)&Ws[kk][tj * 4];
                acc[0][0] += a.x*w.x; acc[0][1] += a.x*w.y; acc[0][2] += a.x*w.z; acc[0][3] += a.x*w.w;
                acc[1][0] += a.y*w.x; acc[1][1] += a.y*w.y; acc[1][2] += a.y*w.z; acc[1][3] += a.y*w.w;
                acc[2][0] += a.z*w.x; acc[2][1] += a.z*w.y; acc[2][2] += a.z*w.z; acc[2][3] += a.z*w.w;
                acc[3][0] += a.w*w.x; acc[3][1] += a.w*w.y; acc[3][2] += a.w*w.z; acc[3][3] += a.w*w.w;
            }
        }

        float* outp = g_part[ks];
#pragma unroll
        for (int bb = 0; bb < 4; bb++) {
            int b = tb * 4 + bb;
            int base = b * FOURH + jbase + tj * 4;
            *(float4*)&outp[base] = make_float4(acc[bb][0], acc[bb][1], acc[bb][2], acc[bb][3]);
        }
    }
}

// Plastic-only kernel for groups 1..3
__global__ __launch_bounds__(256)
void k_plastic(const float* __restrict__ h0, const float* __restrict__ alpha,
               const float* __restrict__ Hebb0, int b0)
{
    plastic_body(blockIdx.x, b0, h0, alpha, Hebb0);
}

// ---------------------------------------------------------------------------
// Pointwise for one group: gates -> h1, c1, tanh_g (GB*Hq elems)
// ---------------------------------------------------------------------------
__global__ __launch_bounds__(256)
void k_pointwise(const float* __restrict__ c0, const float* __restrict__ bias,
                 float* __restrict__ out, int b0)
{
    const int lidx = blockIdx.x * 256 + threadIdx.x;   // 0..GB*Hq-1
    const int b = b0 + (lidx >> 10), h = lidx & 1023;
    const int idx = b * Hq + h;

    float g4[4];
#pragma unroll
    for (int c = 0; c < 4; c++) {
        float v = bias[c * Hq + h];
        int base = b * FOURH + c * Hq + h;
#pragma unroll
        for (int s = 0; s < KSPLIT; s++) v += g_part[s][base];
        g4[c] = v;
    }
    float pl = 0.f;
#pragma unroll
    for (int s = 0; s < PSPLIT; s++) pl += g_plastic_part[(size_t)(b * PSPLIT + s) * Hq + h];
    g4[3] += pl;

    float fg = 1.f / (1.f + expf(-g4[0]));
    float ig = 1.f / (1.f + expf(-g4[1]));
    float og = 1.f / (1.f + expf(-g4[2]));
    float tg = tanhf(g4[3]);
    float c1 = fg * c0[idx] + ig * tg;
    float h1 = og * tanhf(c1);

    out[idx]           = h1;  // h1 block
    out[Bq * Hq + idx] = c1;  // c1 block
    g_tanhg[idx] = tg;
}

// ---------------------------------------------------------------------------
// Hebb update for one group: Hebb1[b,h,i] = clip(Hebb0[b,h,i]+eta*h0[b,h]*tg[b,i])
// 4 rows per block; Hebb0 reads should hit L2 (just streamed by plastic(g)).
// Stores are evict-first so they don't evict the next group's input slice.
// ---------------------------------------------------------------------------
__global__ __launch_bounds__(256)
void k_hebb(const float* __restrict__ Hebb0, const float* __restrict__ h0,
            const float* __restrict__ eta, float* __restrict__ HebbOut, int b0)
{
    const int r0 = (b0 << 10) + blockIdx.x * 4;   // global row group
    const int b  = r0 >> 10;
    const float e = eta[0];
    const int t = threadIdx.x;

    float4 tv = ((const float4*)(g_tanhg + (size_t)b * Hq))[t];

    const float4* in4 = (const float4*)(Hebb0   + (size_t)r0 * Hq) + t;
    float4*       o4  = (float4*)      (HebbOut + (size_t)r0 * Hq) + t;

    float c0f = e * h0[r0 + 0];
    float c1f = e * h0[r0 + 1];
    float c2f = e * h0[r0 + 2];
    float c3f = e * h0[r0 + 3];

    float4 v0 = __ldcs(in4 + 0 * 256);
    float4 v1 = __ldcs(in4 + 1 * 256);
    float4 v2 = __ldcs(in4 + 2 * 256);
    float4 v3 = __ldcs(in4 + 3 * 256);

    float4 o;
    o.x = fminf(1.f, fmaxf(-1.f, fmaf(c0f, tv.x, v0.x)));
    o.y = fminf(1.f, fmaxf(-1.f, fmaf(c0f, tv.y, v0.y)));
    o.z = fminf(1.f, fmaxf(-1.f, fmaf(c0f, tv.z, v0.z)));
    o.w = fminf(1.f, fmaxf(-1.f, fmaf(c0f, tv.w, v0.w)));
    __stcs(o4 + 0 * 256, o);
    o.x = fminf(1.f, fmaxf(-1.f, fmaf(c1f, tv.x, v1.x)));
    o.y = fminf(1.f, fmaxf(-1.f, fmaf(c1f, tv.y, v1.y)));
    o.z = fminf(1.f, fmaxf(-1.f, fmaf(c1f, tv.z, v1.z)));
    o.w = fminf(1.f, fmaxf(-1.f, fmaf(c1f, tv.w, v1.w)));
    __stcs(o4 + 1 * 256, o);
    o.x = fminf(1.f, fmaxf(-1.f, fmaf(c2f, tv.x, v2.x)));
    o.y = fminf(1.f, fmaxf(-1.f, fmaf(c2f, tv.y, v2.y)));
    o.z = fminf(1.f, fmaxf(-1.f, fmaf(c2f, tv.z, v2.z)));
    o.w = fminf(1.f, fmaxf(-1.f, fmaf(c2f, tv.w, v2.w)));
    __stcs(o4 + 2 * 256, o);
    o.x = fminf(1.f, fmaxf(-1.f, fmaf(c3f, tv.x, v3.x)));
    o.y = fminf(1.f, fmaxf(-1.f, fmaf(c3f, tv.y, v3.y)));
    o.z = fminf(1.f, fmaxf(-1.f, fmaf(c3f, tv.z, v3.z)));
    o.w = fminf(1.f, fmaxf(-1.f, fmaf(c3f, tv.w, v3.w)));
    __stcs(o4 + 3 * 256, o);
}

// ---------------------------------------------------------------------------
// Inputs: x, h0, c0, Hebb0, weight_h, weight_x, bias, alpha, eta
// Output: [h1 (B*H) | c1 (B*H) | Hebb1 (B*H*H)] float32
// ---------------------------------------------------------------------------
extern "C" void kernel_launch(void* const* d_in, const int* in_sizes, int n_in,
                              void* d_out, int out_size)
{
    const float* x     = (const float*)d_in[0];
    const float* h0    = (const float*)d_in[1];
    const float* c0    = (const float*)d_in[2];
    const float* Hebb0 = (const float*)d_in[3];
    const float* Wh    = (const float*)d_in[4];
    const float* Wx    = (const float*)d_in[5];
    const float* bias  = (const float*)d_in[6];
    const float* alpha = (const float*)d_in[7];
    const float* eta   = (const float*)d_in[8];
    float* out = (float*)d_out;
    float* HebbOut = out + 2 * Bq * Hq;   // Hebb1 region of the output buffer

    const int pw_grid   = (GB * Hq) / 256;   // 32
    const int hebb_grid = (GB * Hq) / 4;     // 2048

    for (int g = 0; g < NGROUP; g++) {
        const int b0 = g * GB;
        if (g == 0)
            k_group0<<<NGEMM + NPLAST_G, 256>>>(x, h0, Wh, Wx, alpha, Hebb0);
        else
            k_plastic<<<NPLAST_G, 256>>>(h0, alpha, Hebb0, b0);
        k_pointwise<<<pw_grid, 256>>>(c0, bias, out, b0);
        k_hebb<<<hebb_grid, 256>>>(Hebb0, h0, eta, HebbOut, b0);
    }
}

// round 7
// speedup vs baseline: 1.1972x; 1.1972x over previous
#include <cuda_runtime.h>
#include <math.h>
#include <stdint.h>

// Problem dims
#define Bq      32
#define Dq      512
#define Hq      1024
#define FOURH   4096
#define KTOT    1536            // H + D combined reduction dim
#define KSPLIT  8
#define KCHUNK  (KTOT / KSPLIT) // 192
#define PSPLIT  16              // plastic i-splits per batch
#define PCHUNK  (Hq / PSPLIT)   // 64

#define NPLAST  (Bq * PSPLIT)   // 512 plastic blocks (first in grid)
#define NGEMM   (32 * KSPLIT)   // 256 gemm blocks

// Scratch (static __device__ — no allocation)
__device__ float g_part[KSPLIT][Bq * FOURH];        // GEMM partials (4 MB)
__device__ float g_plastic_part[NPLAST * Hq];       // plastic partials (2 MB)
__device__ float g_tanhg[Bq * Hq];                  // tanh(cell gate) (128 KB)

// 16B async copy gmem -> smem, L1-bypass
__device__ __forceinline__ void cp16(uint32_t saddr, const void* gaddr) {
    asm volatile("cp.async.cg.shared.global [%0], [%1], 16;\n"
                 :: "r"(saddr), "l"(gaddr));
}
__device__ __forceinline__ void cp_commit() {
    asm volatile("cp.async.commit_group;\n");
}
__device__ __forceinline__ void cp_wait3() {
    asm volatile("cp.async.wait_group 3;\n");
}

// ---------------------------------------------------------------------------
// K1 (fused): blocks [0,NPLAST) -> plastic partials via cp.async pipeline,
//             blocks [NPLAST, NPLAST+NGEMM) -> gemm partials.
//
// Plastic: partial[b,sp,h] = sum_{i in 64-chunk sp} h0[b,i]*alpha[i,h]*Hebb0[b,i,h]
//   Thread t owns float4 column t. Per i: cp.async 16B alpha + 16B Hebb into a
//   4-stage smem ring (each thread consumes only its own bytes -> no barriers).
//   wait_group 3 keeps 3 stages (24 KB/block) in flight independent of regs.
// ---------------------------------------------------------------------------
__global__ __launch_bounds__(256)
void fused_k1(const float* __restrict__ x,  const float* __restrict__ h0,
              const float* __restrict__ Wh, const float* __restrict__ Wx,
              const float* __restrict__ alpha, const float* __restrict__ Hebb0)
{
    if (blockIdx.x < NPLAST) {
        __shared__ float4 sA[4][256];
        __shared__ float4 sH[4][256];
        __shared__ float h0s[PCHUNK];

        const int b  = blockIdx.x >> 4;
        const int sp = blockIdx.x & 15;
        const int i0 = sp * PCHUNK;
        const int tid = threadIdx.x;

        if (tid < PCHUNK) h0s[tid] = h0[b * Hq + i0 + tid];
        __syncthreads();

        const float* Ag = alpha + (size_t)i0 * Hq + tid * 4;
        const float* Hg = Hebb0 + ((size_t)b * Hq + i0) * Hq + tid * 4;

        const uint32_t aBase = (uint32_t)__cvta_generic_to_shared(&sA[0][tid]);
        const uint32_t hBase = (uint32_t)__cvta_generic_to_shared(&sH[0][tid]);
        const uint32_t slotStride = 256 * 16;   // bytes between ring slots

        // Prologue: stages 0..2
#pragma unroll
        for (int s = 0; s < 3; s++) {
            cp16(aBase + s * slotStride, Ag + (size_t)s * Hq);
            cp16(hBase + s * slotStride, Hg + (size_t)s * Hq);
            cp_commit();
        }

        float4 acc = make_float4(0.f, 0.f, 0.f, 0.f);
        for (int i = 0; i < PCHUNK; i++) {
            const int inext = i + 3;
            if (inext < PCHUNK) {
                const uint32_t sl = (uint32_t)(inext & 3) * slotStride;
                cp16(aBase + sl, Ag + (size_t)inext * Hq);
                cp16(hBase + sl, Hg + (size_t)inext * Hq);
            }
            cp_commit();          // empty group at tail keeps arithmetic uniform
            cp_wait3();           // stage i guaranteed complete

            const int sl = i & 3;
            float4 a = sA[sl][tid];
            float4 v = sH[sl][tid];
            float  s = h0s[i];
            acc.x = fmaf(s, a.x * v.x, acc.x);
            acc.y = fmaf(s, a.y * v.y, acc.y);
            acc.z = fmaf(s, a.z * v.z, acc.z);
            acc.w = fmaf(s, a.w * v.w, acc.w);
        }
        float4* outp = (float4*)(g_plastic_part + (size_t)blockIdx.x * Hq);
        outp[tid] = acc;
    } else {
        // ---------------- gemm partials (R2-proven) ----------------
        __shared__ float Ws[16][128];
        __shared__ float As[16][32];

        const int gid = blockIdx.x - NPLAST;
        const int jt  = gid & 31;       // j tile (128 wide)
        const int ks  = gid >> 5;       // k split (0..7)
        const int tid = threadIdx.x;
        const int tj  = tid & 31;
        const int tb  = tid >> 5;

        float acc[4][4];
#pragma unroll
        for (int i = 0; i < 4; i++)
#pragma unroll
            for (int j = 0; j < 4; j++) acc[i][j] = 0.f;

        const int k0base = ks * KCHUNK;
        const int jbase  = jt * 128;

        for (int t = 0; t < KCHUNK / 16; t++) {
            const int k0 = k0base + t * 16;
            __syncthreads();
#pragma unroll
            for (int r = 0; r < 8; r++) {
                int lin = r * 256 + tid;
                int kk = lin >> 7, j = lin & 127;
                int k = k0 + kk;
                Ws[kk][j] = (k < Hq) ? Wh[(size_t)k * FOURH + jbase + j]
                                     : Wx[(size_t)(k - Hq) * FOURH + jbase + j];
            }
#pragma unroll
            for (int r = 0; r < 2; r++) {
                int lin = r * 256 + tid;
                int kk = lin >> 5, b = lin & 31;
                int k = k0 + kk;
                As[kk][b] = (k < Hq) ? h0[b * Hq + k] : x[b * Dq + (k - Hq)];
            }
            __syncthreads();
#pragma unroll
            for (int kk = 0; kk < 16; kk++) {
                float4 a = *(const float4*)&As[kk][tb * 4];
                float4 w = *(const float4*)&Ws[kk][tj * 4];
                acc[0][0] += a.x*w.x; acc[0][1] += a.x*w.y; acc[0][2] += a.x*w.z; acc[0][3] += a.x*w.w;
                acc[1][0] += a.y*w.x; acc[1][1] += a.y*w.y; acc[1][2] += a.y*w.z; acc[1][3] += a.y*w.w;
                acc[2][0] += a.z*w.x; acc[2][1] += a.z*w.y; acc[2][2] += a.z*w.z; acc[2][3] += a.z*w.w;
                acc[3][0] += a.w*w.x; acc[3][1] += a.w*w.y; acc[3][2] += a.w*w.z; acc[3][3] += a.w*w.w;
            }
        }

        float* outp = g_part[ks];
#pragma unroll
        for (int bb = 0; bb < 4; bb++) {
            int b = tb * 4 + bb;
            int base = b * FOURH + jbase + tj * 4;
            *(float4*)&outp[base] = make_float4(acc[bb][0], acc[bb][1], acc[bb][2], acc[bb][3]);
        }
    }
}

// ---------------------------------------------------------------------------
// K2: pointwise gates -> h1, c1, tanh_g
// ---------------------------------------------------------------------------
__global__ __launch_bounds__(256)
void pointwise_kernel(const float* __restrict__ c0, const float* __restrict__ bias,
                      float* __restrict__ out)
{
    const int idx = blockIdx.x * 256 + threadIdx.x;   // 0..32767
    const int b = idx >> 10, h = idx & 1023;

    float g4[4];
#pragma unroll
    for (int c = 0; c < 4; c++) {
        float v = bias[c * Hq + h];
        int base = b * FOURH + c * Hq + h;
#pragma unroll
        for (int s = 0; s < KSPLIT; s++) v += g_part[s][base];
        g4[c] = v;
    }
    float pl = 0.f;
#pragma unroll
    for (int s = 0; s < PSPLIT; s++) pl += g_plastic_part[(size_t)(b * PSPLIT + s) * Hq + h];
    g4[3] += pl;

    float fg = 1.f / (1.f + expf(-g4[0]));
    float ig = 1.f / (1.f + expf(-g4[1]));
    float og = 1.f / (1.f + expf(-g4[2]));
    float tg = tanhf(g4[3]);
    float c1 = fg * c0[idx] + ig * tg;
    float h1 = og * tanhf(c1);

    out[idx]           = h1;  // h1 block
    out[Bq * Hq + idx] = c1;  // c1 block
    g_tanhg[idx] = tg;
}

// ---------------------------------------------------------------------------
// K3: Hebb1[b,h,i] = clip(Hebb0[b,h,i] + eta*h0[b,h]*tanh_g[b,i], -1, 1)
// 4 rows per block, float4, streaming hints, reversed order for L2 tail reuse.
// ---------------------------------------------------------------------------
__global__ __launch_bounds__(256)
void hebb_kernel(const float* __restrict__ Hebb0, const float* __restrict__ h0,
                 const float* __restrict__ eta, float* __restrict__ HebbOut)
{
    const int r0 = (Bq * Hq - 4) - blockIdx.x * 4;   // reversed, 4-row group
    const int b  = r0 >> 10;
    const float e = eta[0];
    const int t = threadIdx.x;

    float4 tv = ((const float4*)(g_tanhg + (size_t)b * Hq))[t];

    const float4* in4 = (const float4*)(Hebb0   + (size_t)r0 * Hq) + t;
    float4*       o4  = (float4*)      (HebbOut + (size_t)r0 * Hq) + t;

    float c0f = e * h0[r0 + 0];
    float c1f = e * h0[r0 + 1];
    float c2f = e * h0[r0 + 2];
    float c3f = e * h0[r0 + 3];

    float4 v0 = __ldcs(in4 + 0 * 256);
    float4 v1 = __ldcs(in4 + 1 * 256);
    float4 v2 = __ldcs(in4 + 2 * 256);
    float4 v3 = __ldcs(in4 + 3 * 256);

    float4 o;
    o.x = fminf(1.f, fmaxf(-1.f, fmaf(c0f, tv.x, v0.x)));
    o.y = fminf(1.f, fmaxf(-1.f, fmaf(c0f, tv.y, v0.y)));
    o.z = fminf(1.f, fmaxf(-1.f, fmaf(c0f, tv.z, v0.z)));
    o.w = fminf(1.f, fmaxf(-1.f, fmaf(c0f, tv.w, v0.w)));
    __stcs(o4 + 0 * 256, o);
    o.x = fminf(1.f, fmaxf(-1.f, fmaf(c1f, tv.x, v1.x)));
    o.y = fminf(1.f, fmaxf(-1.f, fmaf(c1f, tv.y, v1.y)));
    o.z = fminf(1.f, fmaxf(-1.f, fmaf(c1f, tv.z, v1.z)));
    o.w = fminf(1.f, fmaxf(-1.f, fmaf(c1f, tv.w, v1.w)));
    __stcs(o4 + 1 * 256, o);
    o.x = fminf(1.f, fmaxf(-1.f, fmaf(c2f, tv.x, v2.x)));
    o.y = fminf(1.f, fmaxf(-1.f, fmaf(c2f, tv.y, v2.y)));
    o.z = fminf(1.f, fmaxf(-1.f, fmaf(c2f, tv.z, v2.z)));
    o.w = fminf(1.f, fmaxf(-1.f, fmaf(c2f, tv.w, v2.w)));
    __stcs(o4 + 2 * 256, o);
    o.x = fminf(1.f, fmaxf(-1.f, fmaf(c3f, tv.x, v3.x)));
    o.y = fminf(1.f, fmaxf(-1.f, fmaf(c3f, tv.y, v3.y)));
    o.z = fminf(1.f, fmaxf(-1.f, fmaf(c3f, tv.z, v3.z)));
    o.w = fminf(1.f, fmaxf(-1.f, fmaf(c3f, tv.w, v3.w)));
    __stcs(o4 + 3 * 256, o);
}

// ---------------------------------------------------------------------------
// Inputs: x, h0, c0, Hebb0, weight_h, weight_x, bias, alpha, eta
// Output: [h1 (B*H) | c1 (B*H) | Hebb1 (B*H*H)] float32
// ---------------------------------------------------------------------------
extern "C" void kernel_launch(void* const* d_in, const int* in_sizes, int n_in,
                              void* d_out, int out_size)
{
    const float* x     = (const float*)d_in[0];
    const float* h0    = (const float*)d_in[1];
    const float* c0    = (const float*)d_in[2];
    const float* Hebb0 = (const float*)d_in[3];
    const float* Wh    = (const float*)d_in[4];
    const float* Wx    = (const float*)d_in[5];
    const float* bias  = (const float*)d_in[6];
    const float* alpha = (const float*)d_in[7];
    const float* eta   = (const float*)d_in[8];
    float* out = (float*)d_out;

    fused_k1<<<NPLAST + NGEMM, 256>>>(x, h0, Wh, Wx, alpha, Hebb0);
    pointwise_kernel<<<(Bq * Hq) / 256, 256>>>(c0, bias, out);
    hebb_kernel<<<(Bq * Hq) / 4, 256>>>(Hebb0, h0, eta, out + 2 * Bq * Hq);
}

// round 8
// speedup vs baseline: 1.3043x; 1.0895x over previous
#include <cuda_runtime.h>
#include <math.h>

// Problem dims
#define Bq      32
#define Dq      512
#define Hq      1024
#define FOURH   4096
#define KTOT    1536            // H + D combined reduction dim
#define KSPLIT  8
#define KCHUNK  (KTOT / KSPLIT) // 192
#define PSPLIT  64              // plastic i-splits per batch
#define PCHUNK  (Hq / PSPLIT)   // 16

#define NPLAST  (Bq * PSPLIT)   // 2048 plastic blocks
#define NGEMM   (32 * KSPLIT)   // 256 gemm blocks

// Scratch (static __device__ — no allocation)
__device__ float g_part[KSPLIT][Bq * FOURH];        // GEMM partials (4 MB)
__device__ float g_plastic_part[NPLAST * Hq];       // plastic partials (8 MB)
__device__ float g_tanhg[Bq * Hq];                  // tanh(cell gate) (128 KB)

// ---------------------------------------------------------------------------
// K_gemm: gates partials. C[b][j] = sum_k A[k][b]*W[k][j]
//   A = h0|x concat (k), W = Wh|Wx concat. (jt,ks) -> unique g_part slice.
//   R2-proven body.
// ---------------------------------------------------------------------------
__global__ __launch_bounds__(256)
void k_gemm(const float* __restrict__ x,  const float* __restrict__ h0,
            const float* __restrict__ Wh, const float* __restrict__ Wx)
{
    __shared__ float Ws[16][128];
    __shared__ float As[16][32];

    const int jt  = blockIdx.x & 31;    // j tile (128 wide)
    const int ks  = blockIdx.x >> 5;    // k split (0..7)
    const int tid = threadIdx.x;
    const int tj  = tid & 31;
    const int tb  = tid >> 5;

    float acc[4][4];
#pragma unroll
    for (int i = 0; i < 4; i++)
#pragma unroll
        for (int j = 0; j < 4; j++) acc[i][j] = 0.f;

    const int k0base = ks * KCHUNK;
    const int jbase  = jt * 128;

    for (int t = 0; t < KCHUNK / 16; t++) {
        const int k0 = k0base + t * 16;
        __syncthreads();
#pragma unroll
        for (int r = 0; r < 8; r++) {
            int lin = r * 256 + tid;
            int kk = lin >> 7, j = lin & 127;
            int k = k0 + kk;
            Ws[kk][j] = (k < Hq) ? Wh[(size_t)k * FOURH + jbase + j]
                                 : Wx[(size_t)(k - Hq) * FOURH + jbase + j];
        }
#pragma unroll
        for (int r = 0; r < 2; r++) {
            int lin = r * 256 + tid;
            int kk = lin >> 5, b = lin & 31;
            int k = k0 + kk;
            As[kk][b] = (k < Hq) ? h0[b * Hq + k] : x[b * Dq + (k - Hq)];
        }
        __syncthreads();
#pragma unroll
        for (int kk = 0; kk < 16; kk++) {
            float4 a = *(const float4*)&As[kk][tb * 4];
            float4 w = *(const float4*)&Ws[kk][tj * 4];
            acc[0][0] += a.x*w.x; acc[0][1] += a.x*w.y; acc[0][2] += a.x*w.z; acc[0][3] += a.x*w.w;
            acc[1][0] += a.y*w.x; acc[1][1] += a.y*w.y; acc[1][2] += a.y*w.z; acc[1][3] += a.y*w.w;
            acc[2][0] += a.z*w.x; acc[2][1] += a.z*w.y; acc[2][2] += a.z*w.z; acc[2][3] += a.z*w.w;
            acc[3][0] += a.w*w.x; acc[3][1] += a.w*w.y; acc[3][2] += a.w*w.z; acc[3][3] += a.w*w.w;
        }
    }

    float* outp = g_part[ks];
#pragma unroll
    for (int bb = 0; bb < 4; bb++) {
        int b = tb * 4 + bb;
        int base = b * FOURH + jbase + tj * 4;
        *(float4*)&outp[base] = make_float4(acc[bb][0], acc[bb][1], acc[bb][2], acc[bb][3]);
    }
}

// ---------------------------------------------------------------------------
// K_plastic: hebb-style streaming. 2048 blocks (b, sp), 256 threads, no smem.
// partial[b,sp,h] = sum_{i in 16-chunk sp} h0[b,i]*alpha[i,h]*Hebb0[b,i,h]
// 4-row batches: 8 float4 loads in flight; unroll 1 keeps the batch shape.
// ---------------------------------------------------------------------------
__global__ __launch_bounds__(256)
void k_plastic(const float* __restrict__ h0, const float* __restrict__ alpha,
               const float* __restrict__ Hebb0)
{
    const int b  = blockIdx.x >> 6;
    const int sp = blockIdx.x & 63;
    const int i0 = sp * PCHUNK;
    const int t  = threadIdx.x;

    const float4* Ap  = (const float4*)(alpha + (size_t)i0 * Hq) + t;
    const float4* Hp  = (const float4*)(Hebb0 + ((size_t)b * Hq + i0) * Hq) + t;
    const float*  h0p = h0 + b * Hq + i0;
    const int rs = Hq / 4;   // row stride in float4

    float4 acc = make_float4(0.f, 0.f, 0.f, 0.f);
#pragma unroll 1
    for (int i = 0; i < PCHUNK; i += 4) {
        float4 a0 = Ap[(size_t)(i + 0) * rs];
        float4 v0 = Hp[(size_t)(i + 0) * rs];
        float4 a1 = Ap[(size_t)(i + 1) * rs];
        float4 v1 = Hp[(size_t)(i + 1) * rs];
        float4 a2 = Ap[(size_t)(i + 2) * rs];
        float4 v2 = Hp[(size_t)(i + 2) * rs];
        float4 a3 = Ap[(size_t)(i + 3) * rs];
        float4 v3 = Hp[(size_t)(i + 3) * rs];
        float s0 = __ldg(h0p + i + 0);
        float s1 = __ldg(h0p + i + 1);
        float s2 = __ldg(h0p + i + 2);
        float s3 = __ldg(h0p + i + 3);
        acc.x = fmaf(s0, a0.x * v0.x, acc.x);
        acc.y = fmaf(s0, a0.y * v0.y, acc.y);
        acc.z = fmaf(s0, a0.z * v0.z, acc.z);
        acc.w = fmaf(s0, a0.w * v0.w, acc.w);
        acc.x = fmaf(s1, a1.x * v1.x, acc.x);
        acc.y = fmaf(s1, a1.y * v1.y, acc.y);
        acc.z = fmaf(s1, a1.z * v1.z, acc.z);
        acc.w = fmaf(s1, a1.w * v1.w, acc.w);
        acc.x = fmaf(s2, a2.x * v2.x, acc.x);
        acc.y = fmaf(s2, a2.y * v2.y, acc.y);
        acc.z = fmaf(s2, a2.z * v2.z, acc.z);
        acc.w = fmaf(s2, a2.w * v2.w, acc.w);
        acc.x = fmaf(s3, a3.x * v3.x, acc.x);
        acc.y = fmaf(s3, a3.y * v3.y, acc.y);
        acc.z = fmaf(s3, a3.z * v3.z, acc.z);
        acc.w = fmaf(s3, a3.w * v3.w, acc.w);
    }
    ((float4*)(g_plastic_part + (size_t)blockIdx.x * Hq))[t] = acc;
}

// ---------------------------------------------------------------------------
// K2: pointwise gates -> h1, c1, tanh_g
// ---------------------------------------------------------------------------
__global__ __launch_bounds__(256)
void pointwise_kernel(const float* __restrict__ c0, const float* __restrict__ bias,
                      float* __restrict__ out)
{
    const int idx = blockIdx.x * 256 + threadIdx.x;   // 0..32767
    const int b = idx >> 10, h = idx & 1023;

    float g4[4];
#pragma unroll
    for (int c = 0; c < 4; c++) {
        float v = bias[c * Hq + h];
        int base = b * FOURH + c * Hq + h;
#pragma unroll
        for (int s = 0; s < KSPLIT; s++) v += g_part[s][base];
        g4[c] = v;
    }
    float pl = 0.f;
#pragma unroll
    for (int s = 0; s < PSPLIT; s++)
        pl += g_plastic_part[(size_t)(b * PSPLIT + s) * Hq + h];
    g4[3] += pl;

    float fg = 1.f / (1.f + expf(-g4[0]));
    float ig = 1.f / (1.f + expf(-g4[1]));
    float og = 1.f / (1.f + expf(-g4[2]));
    float tg = tanhf(g4[3]);
    float c1 = fg * c0[idx] + ig * tg;
    float h1 = og * tanhf(c1);

    out[idx]           = h1;  // h1 block
    out[Bq * Hq + idx] = c1;  // c1 block
    g_tanhg[idx] = tg;
}

// ---------------------------------------------------------------------------
// K3: Hebb1[b,h,i] = clip(Hebb0[b,h,i] + eta*h0[b,h]*tanh_g[b,i], -1, 1)
// 4 rows per block, float4, streaming hints, reversed order for L2 tail reuse.
// ---------------------------------------------------------------------------
__global__ __launch_bounds__(256)
void hebb_kernel(const float* __restrict__ Hebb0, const float* __restrict__ h0,
                 const float* __restrict__ eta, float* __restrict__ HebbOut)
{
    const int r0 = (Bq * Hq - 4) - blockIdx.x * 4;   // reversed, 4-row group
    const int b  = r0 >> 10;
    const float e = eta[0];
    const int t = threadIdx.x;

    float4 tv = ((const float4*)(g_tanhg + (size_t)b * Hq))[t];

    const float4* in4 = (const float4*)(Hebb0   + (size_t)r0 * Hq) + t;
    float4*       o4  = (float4*)      (HebbOut + (size_t)r0 * Hq) + t;

    float c0f = e * h0[r0 + 0];
    float c1f = e * h0[r0 + 1];
    float c2f = e * h0[r0 + 2];
    float c3f = e * h0[r0 + 3];

    float4 v0 = __ldcs(in4 + 0 * 256);
    float4 v1 = __ldcs(in4 + 1 * 256);
    float4 v2 = __ldcs(in4 + 2 * 256);
    float4 v3 = __ldcs(in4 + 3 * 256);

    float4 o;
    o.x = fminf(1.f, fmaxf(-1.f, fmaf(c0f, tv.x, v0.x)));
    o.y = fminf(1.f, fmaxf(-1.f, fmaf(c0f, tv.y, v0.y)));
    o.z = fminf(1.f, fmaxf(-1.f, fmaf(c0f, tv.z, v0.z)));
    o.w = fminf(1.f, fmaxf(-1.f, fmaf(c0f, tv.w, v0.w)));
    __stcs(o4 + 0 * 256, o);
    o.x = fminf(1.f, fmaxf(-1.f, fmaf(c1f, tv.x, v1.x)));
    o.y = fminf(1.f, fmaxf(-1.f, fmaf(c1f, tv.y, v1.y)));
    o.z = fminf(1.f, fmaxf(-1.f, fmaf(c1f, tv.z, v1.z)));
    o.w = fminf(1.f, fmaxf(-1.f, fmaf(c1f, tv.w, v1.w)));
    __stcs(o4 + 1 * 256, o);
    o.x = fminf(1.f, fmaxf(-1.f, fmaf(c2f, tv.x, v2.x)));
    o.y = fminf(1.f, fmaxf(-1.f, fmaf(c2f, tv.y, v2.y)));
    o.z = fminf(1.f, fmaxf(-1.f, fmaf(c2f, tv.z, v2.z)));
    o.w = fminf(1.f, fmaxf(-1.f, fmaf(c2f, tv.w, v2.w)));
    __stcs(o4 + 2 * 256, o);
    o.x = fminf(1.f, fmaxf(-1.f, fmaf(c3f, tv.x, v3.x)));
    o.y = fminf(1.f, fmaxf(-1.f, fmaf(c3f, tv.y, v3.y)));
    o.z = fminf(1.f, fmaxf(-1.f, fmaf(c3f, tv.z, v3.z)));
    o.w = fminf(1.f, fmaxf(-1.f, fmaf(c3f, tv.w, v3.w)));
    __stcs(o4 + 3 * 256, o);
}

// ---------------------------------------------------------------------------
// Inputs: x, h0, c0, Hebb0, weight_h, weight_x, bias, alpha, eta
// Output: [h1 (B*H) | c1 (B*H) | Hebb1 (B*H*H)] float32
// ---------------------------------------------------------------------------
extern "C" void kernel_launch(void* const* d_in, const int* in_sizes, int n_in,
                              void* d_out, int out_size)
{
    const float* x     = (const float*)d_in[0];
    const float* h0    = (const float*)d_in[1];
    const float* c0    = (const float*)d_in[2];
    const float* Hebb0 = (const float*)d_in[3];
    const float* Wh    = (const float*)d_in[4];
    const float* Wx    = (const float*)d_in[5];
    const float* bias  = (const float*)d_in[6];
    const float* eta   = (const float*)d_in[8];
    const float* alpha = (const float*)d_in[7];
    float* out = (float*)d_out;

    k_gemm<<<NGEMM, 256>>>(x, h0, Wh, Wx);
    k_plastic<<<NPLAST, 256>>>(h0, alpha, Hebb0);
    pointwise_kernel<<<(Bq * Hq) / 256, 256>>>(c0, bias, out);
    hebb_kernel<<<(Bq * Hq) / 4, 256>>>(Hebb0, h0, eta, out + 2 * Bq * Hq);
}